// round 2
// baseline (speedup 1.0000x reference)
#include <cuda_runtime.h>
#include <cstdint>
#include <math.h>

// ============================================================
// Problem constants (fixed by the reference)
//   x:   (4096, 2048) f32      W1: (2048, 512)   b1: (512)
//   W2:  (512, 128)            b2: (128)
//   asz: (4, 12, 3)            out: (4096) f32
// ============================================================

__device__ float g_H[4096 * 512];    // relu(x@W1+b1) scratch (8 MB)
__device__ float g_com[4096 * 128];  // com_params scratch (2 MB)

// ------------------------------------------------------------
// SGEMM (fp32, smem tiled): C = [relu](A @ B + bias)
// ------------------------------------------------------------
template<int BM, int BN, int BK, int TM, int TN, bool RELU>
__device__ __forceinline__ void sgemm_body(
    const float* __restrict__ A, const float* __restrict__ Bm,
    const float* __restrict__ bias, float* __restrict__ C,
    int M, int N, int K)
{
    __shared__ float As[BK][BM];
    __shared__ float Bs[BK][BN];
    const int tid = threadIdx.x;
    const int NX = BN / TN;            // 16
    const int tx = tid % NX;
    const int ty = tid / NX;
    const int bm = blockIdx.y * BM;
    const int bn = blockIdx.x * BN;

    float acc[TM][TN];
#pragma unroll
    for (int i = 0; i < TM; ++i)
#pragma unroll
        for (int j = 0; j < TN; ++j) acc[i][j] = 0.f;

    for (int kt = 0; kt < K; kt += BK) {
        // A tile (BM x BK), stored transposed As[k][m]
#pragma unroll
        for (int l = 0; l < (BM * BK) / (256 * 4); ++l) {
            int id  = tid + l * 256;
            int row = id / (BK / 4);
            int c   = id % (BK / 4);
            float4 v = *reinterpret_cast<const float4*>(
                A + (size_t)(bm + row) * K + kt + c * 4);
            As[c*4+0][row] = v.x; As[c*4+1][row] = v.y;
            As[c*4+2][row] = v.z; As[c*4+3][row] = v.w;
        }
        // B tile (BK x BN)
#pragma unroll
        for (int l = 0; l < (BK * BN) / (256 * 4); ++l) {
            int id = tid + l * 256;
            int kr = id / (BN / 4);
            int c  = id % (BN / 4);
            *reinterpret_cast<float4*>(&Bs[kr][c*4]) =
                *reinterpret_cast<const float4*>(
                    Bm + (size_t)(kt + kr) * N + bn + c * 4);
        }
        __syncthreads();
#pragma unroll
        for (int k = 0; k < BK; ++k) {
            float ra[TM], rb[TN];
#pragma unroll
            for (int i = 0; i < TM; i += 4)
                *reinterpret_cast<float4*>(&ra[i]) =
                    *reinterpret_cast<const float4*>(&As[k][ty*TM + i]);
#pragma unroll
            for (int j = 0; j < TN; j += 4)
                *reinterpret_cast<float4*>(&rb[j]) =
                    *reinterpret_cast<const float4*>(&Bs[k][tx*TN + j]);
#pragma unroll
            for (int i = 0; i < TM; ++i)
#pragma unroll
                for (int j = 0; j < TN; ++j)
                    acc[i][j] = fmaf(ra[i], rb[j], acc[i][j]);
        }
        __syncthreads();
    }
#pragma unroll
    for (int i = 0; i < TM; ++i) {
        int row = bm + ty * TM + i;
#pragma unroll
        for (int j = 0; j < TN; ++j) {
            int col = bn + tx * TN + j;
            float v = acc[i][j] + bias[col];
            if (RELU) v = fmaxf(v, 0.f);
            C[(size_t)row * N + col] = v;
        }
    }
}

__global__ void __launch_bounds__(256)
gemm1_kernel(const float* __restrict__ x, const float* __restrict__ W1,
             const float* __restrict__ b1)
{
    sgemm_body<128, 64, 16, 8, 4, true>(x, W1, b1, g_H, 4096, 512, 2048);
}

__global__ void __launch_bounds__(256)
gemm2_kernel(const float* __restrict__ W2, const float* __restrict__ b2)
{
    sgemm_body<128, 64, 16, 8, 4, false>(g_H, W2, b2, g_com, 4096, 128, 512);
}

// ------------------------------------------------------------
// Quantum circuit kernel.
//
// State lives in smem (4096 complex = 32 KB), one CTA per batch elem.
// CNOT layers are GF(2)-linear index maps, tracked host-side and
// folded into each Rot gate's pairing mask (colmask) + orientation
// parity row (rowmask). Initial H+FRQI and final FRQI+H+measure are
// closed-form (init / weighted reduction).
// ------------------------------------------------------------
struct GateMeta {
    unsigned colmask[48];   // physical XOR partner mask per Rot gate
    unsigned rowmask[48];   // parity mask: parity(row & p)==0 -> logical |0>
    unsigned lfmask[11];    // final phi basis masks, bit-reversed order
    unsigned cz;            // phi(wire-0 bit)
};

__global__ void __launch_bounds__(256)
circuit_kernel(const float* __restrict__ x, const float* __restrict__ asz,
               float* __restrict__ out, GateMeta meta)
{
    __shared__ float2 st[4096];
    __shared__ float2 mats[48][4];
    __shared__ float  wsum[8];
    const int b   = blockIdx.x;
    const int tid = threadIdx.x;

    // Rot matrices from asz_params: m00=e^{-i(p+o)/2}c, m01=-e^{i(p-o)/2}s,
    //                               m10=e^{-i(p-o)/2}s, m11=e^{i(p+o)/2}c
    if (tid < 48) {
        float phi = asz[tid*3+0], th = asz[tid*3+1], om = asz[tid*3+2];
        float c, s, cp, sp, cm, sm;
        sincosf(0.5f * th, &s, &c);
        sincosf(0.5f * (phi + om), &sp, &cp);
        sincosf(0.5f * (phi - om), &sm, &cm);
        mats[tid][0] = make_float2( cp * c, -sp * c);
        mats[tid][1] = make_float2(-cm * s, -sm * s);
        mats[tid][2] = make_float2( cm * s, -sm * s);
        mats[tid][3] = make_float2( cp * c,  sp * c);
    }
#pragma unroll
    for (int i = 0; i < 16; ++i) st[tid + i * 256] = make_float2(0.f, 0.f);
    __syncthreads();

    // Closed-form init: after H on wires 1..7 and FRQI(com, q=7):
    // st[j*16] = 2^-3.5 cos(a_j/2), st[2048+j*16] = 2^-3.5 sin(a_j/2),
    // a_j = com[b, rev7(j)]. Iterate in com-order for coalescing.
    if (tid < 128) {
        const float inv = 0.08838834764831844f;  // 2^-3.5
        float a = 0.5f * g_com[b * 128 + tid];
        float sa, ca; sincosf(a, &sa, &ca);
        int j = (int)(__brev((unsigned)tid) >> 25);  // rev7
        st[j * 16]        = make_float2(ca * inv, 0.f);
        st[2048 + j * 16] = make_float2(sa * inv, 0.f);
    }
    __syncthreads();

    // 48 Rot gates (CNOTs folded into masks; no state permutation ever)
    for (int g = 0; g < 48; ++g) {
        const unsigned cmk = meta.colmask[g];
        const unsigned rmk = meta.rowmask[g];
        const unsigned low = (cmk & (0u - cmk)) - 1u;  // pivot-1
        const float2 m00 = mats[g][0], m01 = mats[g][1];
        const float2 m10 = mats[g][2], m11 = mats[g][3];
#pragma unroll
        for (int i = 0; i < 8; ++i) {
            unsigned k  = tid + i * 256;
            unsigned p0 = ((k & ~low) << 1) | (k & low);  // pivot bit = 0
            unsigned p1 = p0 ^ cmk;
            unsigned lb = __popc(rmk & p0) & 1u;          // logical bit of p0
            unsigned i0 = lb ? p1 : p0;                   // logical |0> slot
            unsigned i1 = lb ? p0 : p1;
            float2 s0 = st[i0];
            float2 s1 = st[i1];
            float2 n0, n1;
            n0.x = m00.x*s0.x - m00.y*s0.y + m01.x*s1.x - m01.y*s1.y;
            n0.y = m00.x*s0.y + m00.y*s0.x + m01.x*s1.y + m01.y*s1.x;
            n1.x = m10.x*s0.x - m10.y*s0.y + m11.x*s1.x - m11.y*s1.y;
            n1.y = m10.x*s0.y + m10.y*s0.x + m11.x*s1.y + m11.y*s1.x;
            st[i0] = n0;
            st[i1] = n1;
        }
        __syncthreads();
    }

    // Final FRQI(img=-x, q=11) + H^11 + measurement collapse into:
    //   sum_j cos(x_jr)(|s1|^2-|s0|^2) - 2 sin(x_jr) Re(conj(s0) s1)
    // Iterate idx = rev11(j) so x reads are coalesced; smem gather is cheap.
    float acc = 0.f;
#pragma unroll
    for (int i = 0; i < 8; ++i) {
        unsigned idx = tid + i * 256;
        unsigned m0 = 0;
#pragma unroll
        for (int q = 0; q < 11; ++q)
            m0 ^= (0u - ((idx >> q) & 1u)) & meta.lfmask[q];
        unsigned m1 = m0 ^ meta.cz;
        float2 s0 = st[m0];
        float2 s1 = st[m1];
        float xv = x[(size_t)b * 2048 + idx];
        float sv, cv;
        sincosf(xv, &sv, &cv);
        acc += cv * ((s1.x*s1.x + s1.y*s1.y) - (s0.x*s0.x + s0.y*s0.y))
             - 2.f * sv * (s0.x*s1.x + s0.y*s1.y);
    }
#pragma unroll
    for (int o = 16; o > 0; o >>= 1)
        acc += __shfl_down_sync(0xffffffffu, acc, o);
    if ((tid & 31) == 0) wsum[tid >> 5] = acc;
    __syncthreads();
    if (tid == 0) {
        float v = 0.f;
#pragma unroll
        for (int w = 0; w < 8; ++w) v += wsum[w];
        out[b] = v;
    }
}

// ------------------------------------------------------------
// Host: GF(2) bookkeeping for the CNOT layers.
//
// phi: logical index -> physical index; logical[i] = physical[phi(i)].
// Reference CNOT layer (w = 0..11 applied sequentially to the state)
// acts on indices as  new[i] = old[M_c0(M_c1(...M_c11(i)...))]
// (last CNOT innermost). Since we never move data:
//     phi <- phi o M_seq,   M_seq = CNOT index-maps applied in
//                           REVERSE wire order (each CNOT self-inverse).
// ------------------------------------------------------------
static unsigned gf2_cnot_rev(unsigned v, int r) {
    // M_seq(v): apply CNOT(w, (w+r)%12) index-map for w = 11..0.
    // wire w <-> bit (11-w). CNOT map: flip tgt bit if ctrl bit set.
    for (int w = 11; w >= 0; --w) {
        int t = (w + r) % 12;
        if ((v >> (11 - w)) & 1u) v ^= 1u << (11 - t);
    }
    return v;
}

static void build_meta(GateMeta& meta) {
    unsigned macc[12];                       // macc[p] = phi(e_p) (columns)
    for (int p = 0; p < 12; ++p) macc[p] = 1u << p;
    int g = 0;
    for (int l = 0; l < 4; ++l) {
        // rows of phi^{-1} via Gaussian elimination over GF(2)
        unsigned row[12], aug[12];
        for (int p = 0; p < 12; ++p) {
            unsigned rr = 0;
            for (int q = 0; q < 12; ++q) rr |= ((macc[q] >> p) & 1u) << q;
            row[p] = rr; aug[p] = 1u << p;
        }
        for (int i = 0; i < 12; ++i) {
            int piv = i;
            while (!((row[piv] >> i) & 1u)) ++piv;
            unsigned t = row[i]; row[i] = row[piv]; row[piv] = t;
            t = aug[i]; aug[i] = aug[piv]; aug[piv] = t;
            for (int jj = 0; jj < 12; ++jj)
                if (jj != i && ((row[jj] >> i) & 1u)) {
                    row[jj] ^= row[i]; aug[jj] ^= aug[i];
                }
        }
        // Rot gates of layer l use the pre-layer phi
        for (int w = 0; w < 12; ++w) {
            meta.colmask[g] = macc[11 - w];  // phi(e_{11-w})
            meta.rowmask[g] = aug[11 - w];   // row (11-w) of phi^{-1}
            ++g;
        }
        // phi <- phi o M_seq  (column p: phi(M_seq(e_p)))
        int r = l % 11 + 1;
        unsigned nmacc[12];
        for (int p = 0; p < 12; ++p) {
            unsigned u = gf2_cnot_rev(1u << p, r);
            unsigned acc = 0;
            for (int q = 0; q < 12; ++q)
                if ((u >> q) & 1u) acc ^= macc[q];
            nmacc[p] = acc;
        }
        for (int p = 0; p < 12; ++p) macc[p] = nmacc[p];
    }
    // final masks, pre-bit-reversed so the kernel iterates idx = rev11(j)
    for (int q = 0; q < 11; ++q) meta.lfmask[q] = macc[10 - q];
    meta.cz = macc[11];
}

// ------------------------------------------------------------
extern "C" void kernel_launch(void* const* d_in, const int* in_sizes, int n_in,
                              void* d_out, int out_size)
{
    const float* x   = (const float*)d_in[0];
    const float* W1  = (const float*)d_in[1];
    const float* b1  = (const float*)d_in[2];
    const float* W2  = (const float*)d_in[3];
    const float* b2  = (const float*)d_in[4];
    const float* asz = (const float*)d_in[5];
    float* out = (float*)d_out;

    GateMeta meta;
    build_meta(meta);

    dim3 g1(512 / 64, 4096 / 128);
    gemm1_kernel<<<g1, 256>>>(x, W1, b1);
    dim3 g2(128 / 64, 4096 / 128);
    gemm2_kernel<<<g2, 256>>>(W2, b2);
    circuit_kernel<<<4096, 256>>>(x, asz, out, meta);
}

// round 3
// speedup vs baseline: 1.0427x; 1.0427x over previous
#include <cuda_runtime.h>
#include <cstdint>
#include <math.h>

typedef unsigned long long ull;

// ============================================================
// Problem constants (fixed by the reference)
//   x:   (4096, 2048) f32      W1: (2048, 512)   b1: (512)
//   W2:  (512, 128)            b2: (128)
//   asz: (4, 12, 3)            out: (4096) f32
// ============================================================

__device__ float g_H[4096 * 512];    // relu(x@W1+b1) scratch (8 MB)
__device__ float g_com[4096 * 128];  // com_params scratch (2 MB)

// ------------------------------------------------------------
// f32x2 helpers (Blackwell packed fp32: 2 lanes per fma slot)
// ------------------------------------------------------------
__device__ __forceinline__ ull f2mul(ull a, ull b) {
    ull d; asm("mul.rn.f32x2 %0, %1, %2;" : "=l"(d) : "l"(a), "l"(b)); return d;
}
__device__ __forceinline__ ull f2fma(ull a, ull b, ull c) {
    ull d; asm("fma.rn.f32x2 %0, %1, %2, %3;" : "=l"(d) : "l"(a), "l"(b), "l"(c)); return d;
}
__device__ __forceinline__ ull pack2(float lo, float hi) {
    ull r; asm("mov.b64 %0, {%1, %2};" : "=l"(r) : "f"(lo), "f"(hi)); return r;
}
__device__ __forceinline__ float2 unpack2(ull v) {
    float2 r; asm("mov.b64 {%0, %1}, %2;" : "=f"(r.x), "=f"(r.y) : "l"(v)); return r;
}
__device__ __forceinline__ ull uswap(ull v) {
    float2 r = unpack2(v);
    return pack2(r.y, r.x);
}

// ------------------------------------------------------------
// SGEMM (fp32, smem tiled, f32x2 accumulators packed along M):
// C = [relu](A @ B + bias)
// ------------------------------------------------------------
template<int BM, int BN, int BK, int TM, int TN, bool RELU>
__device__ __forceinline__ void sgemm_body(
    const float* __restrict__ A, const float* __restrict__ Bm,
    const float* __restrict__ bias, float* __restrict__ C,
    int M, int N, int K)
{
    __shared__ float As[BK][BM];
    __shared__ float Bs[BK][BN];
    const int tid = threadIdx.x;
    const int NX = BN / TN;            // 16
    const int tx = tid % NX;
    const int ty = tid / NX;
    const int bm = blockIdx.y * BM;
    const int bn = blockIdx.x * BN;

    ull acc[TM / 2][TN];
#pragma unroll
    for (int i = 0; i < TM / 2; ++i)
#pragma unroll
        for (int j = 0; j < TN; ++j) acc[i][j] = 0ull;

    for (int kt = 0; kt < K; kt += BK) {
        // A tile (BM x BK), stored transposed As[k][m]
#pragma unroll
        for (int l = 0; l < (BM * BK) / (256 * 4); ++l) {
            int id  = tid + l * 256;
            int row = id / (BK / 4);
            int c   = id % (BK / 4);
            float4 v = *reinterpret_cast<const float4*>(
                A + (size_t)(bm + row) * K + kt + c * 4);
            As[c*4+0][row] = v.x; As[c*4+1][row] = v.y;
            As[c*4+2][row] = v.z; As[c*4+3][row] = v.w;
        }
        // B tile (BK x BN)
#pragma unroll
        for (int l = 0; l < (BK * BN) / (256 * 4); ++l) {
            int id = tid + l * 256;
            int kr = id / (BN / 4);
            int c  = id % (BN / 4);
            *reinterpret_cast<float4*>(&Bs[kr][c*4]) =
                *reinterpret_cast<const float4*>(
                    Bm + (size_t)(kt + kr) * N + bn + c * 4);
        }
        __syncthreads();
#pragma unroll
        for (int k = 0; k < BK; ++k) {
            ull ra[TM / 2];
            float rb[TN];
#pragma unroll
            for (int i = 0; i < TM / 2; ++i)
                ra[i] = *reinterpret_cast<const ull*>(&As[k][ty*TM + 2*i]);
#pragma unroll
            for (int j = 0; j < TN; j += 4)
                *reinterpret_cast<float4*>(&rb[j]) =
                    *reinterpret_cast<const float4*>(&Bs[k][tx*TN + j]);
#pragma unroll
            for (int j = 0; j < TN; ++j) {
                ull rbb = pack2(rb[j], rb[j]);
#pragma unroll
                for (int i = 0; i < TM / 2; ++i)
                    acc[i][j] = f2fma(ra[i], rbb, acc[i][j]);
            }
        }
        __syncthreads();
    }
#pragma unroll
    for (int i = 0; i < TM / 2; ++i) {
        int row = bm + ty * TM + 2 * i;
#pragma unroll
        for (int j = 0; j < TN; ++j) {
            int col = bn + tx * TN + j;
            float2 u = unpack2(acc[i][j]);
            float vlo = u.x + bias[col];
            float vhi = u.y + bias[col];
            if (RELU) { vlo = fmaxf(vlo, 0.f); vhi = fmaxf(vhi, 0.f); }
            C[(size_t)row * N + col]       = vlo;
            C[(size_t)(row + 1) * N + col] = vhi;
        }
    }
}

__global__ void __launch_bounds__(256)
gemm1_kernel(const float* __restrict__ x, const float* __restrict__ W1,
             const float* __restrict__ b1)
{
    sgemm_body<128, 64, 16, 8, 4, true>(x, W1, b1, g_H, 4096, 512, 2048);
}

__global__ void __launch_bounds__(256)
gemm2_kernel(const float* __restrict__ W2, const float* __restrict__ b2)
{
    sgemm_body<128, 64, 16, 8, 4, false>(g_H, W2, b2, g_com, 4096, 128, 512);
}

// ------------------------------------------------------------
// Quantum circuit kernel.
//
// State in smem (4096 complex = 32 KB), one CTA per batch elem.
// CNOT layers are GF(2)-linear index maps tracked host-side.
// 4 commuting Rot gates (same layer, distinct wires) are fused per
// sweep: each thread owns one 16-element XOR-orbit in registers.
// All complex 2x2 math is f32x2-packed (re,im per b64 lane pair).
// ------------------------------------------------------------
struct GroupMeta {
    unsigned cmk[4];    // physical XOR partner masks (4 gates)
    unsigned rmk[4];    // parity rows of phi^{-1} (orientation)
    unsigned d[8];      // complement basis: orbit reps = span(d)
    int      gidx[4];   // gate index into mats (asz order)
};
struct CircMeta {
    GroupMeta grp[12];
    unsigned lfmask[11];  // final phi basis masks, bit-reversed order
    unsigned cz;          // phi(wire-0 bit)
};

__global__ void __launch_bounds__(256)
circuit_kernel(const float* __restrict__ x, const float* __restrict__ asz,
               float* __restrict__ out, CircMeta meta)
{
    __shared__ float2 st[4096];
    __shared__ ull    mats[48][8];   // packed rot-matrix constants
    __shared__ float  wsum[8];
    const int b   = blockIdx.x;
    const int tid = threadIdx.x;
    ull* stq = reinterpret_cast<ull*>(st);

    // Rot matrix packs from asz_params:
    // m00=e^{-i(p+o)/2}c, m01=-e^{i(p-o)/2}s, m10=e^{-i(p-o)/2}s, m11=e^{i(p+o)/2}c
    // pack layout per entry m: [re] = (m.x, m.x), [im] = (-m.y, m.y)
    if (tid < 48) {
        float phi = asz[tid*3+0], th = asz[tid*3+1], om = asz[tid*3+2];
        float c, s, cp, sp, cm, sm;
        sincosf(0.5f * th, &s, &c);
        sincosf(0.5f * (phi + om), &sp, &cp);
        sincosf(0.5f * (phi - om), &sm, &cm);
        float2 m00 = make_float2( cp * c, -sp * c);
        float2 m01 = make_float2(-cm * s, -sm * s);
        float2 m10 = make_float2( cm * s, -sm * s);
        float2 m11 = make_float2( cp * c,  sp * c);
        mats[tid][0] = pack2(m00.x, m00.x); mats[tid][1] = pack2(-m00.y, m00.y);
        mats[tid][2] = pack2(m01.x, m01.x); mats[tid][3] = pack2(-m01.y, m01.y);
        mats[tid][4] = pack2(m10.x, m10.x); mats[tid][5] = pack2(-m10.y, m10.y);
        mats[tid][6] = pack2(m11.x, m11.x); mats[tid][7] = pack2(-m11.y, m11.y);
    }
#pragma unroll
    for (int i = 0; i < 16; ++i) st[tid + i * 256] = make_float2(0.f, 0.f);
    __syncthreads();

    // Closed-form init: after H on wires 1..7 and FRQI(com, q=7):
    // st[j*16] = 2^-3.5 cos(a_j/2), st[2048+j*16] = 2^-3.5 sin(a_j/2),
    // a_j = com[b, rev7(j)].
    if (tid < 128) {
        const float inv = 0.08838834764831844f;  // 2^-3.5
        float a = 0.5f * g_com[b * 128 + tid];
        float sa, ca; sincosf(a, &sa, &ca);
        int j = (int)(__brev((unsigned)tid) >> 25);  // rev7
        st[j * 16]        = make_float2(ca * inv, 0.f);
        st[2048 + j * 16] = make_float2(sa * inv, 0.f);
    }
    __syncthreads();

    // 12 fused sweeps of 4 commuting Rot gates each
#pragma unroll 1
    for (int G = 0; G < 12; ++G) {
        const GroupMeta& gm = meta.grp[G];
        unsigned rep = 0;
#pragma unroll
        for (int j = 0; j < 8; ++j)
            rep ^= ((tid >> j) & 1u) ? gm.d[j] : 0u;

        unsigned idx[16];
#pragma unroll
        for (int bb = 0; bb < 16; ++bb) {
            unsigned o = rep;
            if (bb & 1) o ^= gm.cmk[0];
            if (bb & 2) o ^= gm.cmk[1];
            if (bb & 4) o ^= gm.cmk[2];
            if (bb & 8) o ^= gm.cmk[3];
            idx[bb] = o;
        }
        ull v[16];
#pragma unroll
        for (int bb = 0; bb < 16; ++bb) v[bb] = stq[idx[bb]];

#pragma unroll
        for (int gg = 0; gg < 4; ++gg) {
            const ull* mp = mats[gm.gidx[gg]];
            bool lb = (__popc(gm.rmk[gg] & rep) & 1) != 0;
            // lb==0: rows (m00 m01 / m10 m11); lb==1: swapped (m11 m10 / m01 m00)
            ull a0r = lb ? mp[6] : mp[0], a0i = lb ? mp[7] : mp[1];
            ull a1r = lb ? mp[4] : mp[2], a1i = lb ? mp[5] : mp[3];
            ull b0r = lb ? mp[2] : mp[4], b0i = lb ? mp[3] : mp[5];
            ull b1r = lb ? mp[0] : mp[6], b1i = lb ? mp[1] : mp[7];
            const unsigned bit = 1u << gg;
#pragma unroll
            for (int bb = 0; bb < 16; ++bb) {
                if (bb & bit) continue;
                ull s0 = v[bb], s1 = v[bb ^ bit];
                ull s0s = uswap(s0), s1s = uswap(s1);
                ull n0 = f2mul(a0r, s0);
                n0 = f2fma(a0i, s0s, n0);
                n0 = f2fma(a1r, s1, n0);
                n0 = f2fma(a1i, s1s, n0);
                ull n1 = f2mul(b0r, s0);
                n1 = f2fma(b0i, s0s, n1);
                n1 = f2fma(b1r, s1, n1);
                n1 = f2fma(b1i, s1s, n1);
                v[bb] = n0; v[bb ^ bit] = n1;
            }
        }
#pragma unroll
        for (int bb = 0; bb < 16; ++bb) stq[idx[bb]] = v[bb];
        __syncthreads();
    }

    // Final FRQI(img=-x, q=11) + H^11 + measurement collapse into:
    //   sum_j cos(x_jr)(|s1|^2-|s0|^2) - 2 sin(x_jr) Re(conj(s0) s1)
    // Iterate idx = rev11(j) so x reads are coalesced.
    float acc = 0.f;
#pragma unroll
    for (int i = 0; i < 8; ++i) {
        unsigned idx = tid + i * 256;
        unsigned m0 = 0;
#pragma unroll
        for (int q = 0; q < 11; ++q)
            m0 ^= (0u - ((idx >> q) & 1u)) & meta.lfmask[q];
        unsigned m1 = m0 ^ meta.cz;
        float2 s0 = st[m0];
        float2 s1 = st[m1];
        float xv = x[(size_t)b * 2048 + idx];
        float sv, cv;
        sincosf(xv, &sv, &cv);
        acc += cv * ((s1.x*s1.x + s1.y*s1.y) - (s0.x*s0.x + s0.y*s0.y))
             - 2.f * sv * (s0.x*s1.x + s0.y*s1.y);
    }
#pragma unroll
    for (int o = 16; o > 0; o >>= 1)
        acc += __shfl_down_sync(0xffffffffu, acc, o);
    if ((tid & 31) == 0) wsum[tid >> 5] = acc;
    __syncthreads();
    if (tid == 0) {
        float v = 0.f;
#pragma unroll
        for (int w = 0; w < 8; ++w) v += wsum[w];
        out[b] = v;
    }
}

// ------------------------------------------------------------
// Host: GF(2) bookkeeping for the CNOT layers.
//
// phi: logical index -> physical index; logical[i] = physical[phi(i)].
// Reference CNOT layer (w = 0..11 sequential on the state) acts on
// indices as new[i] = old[M_c0(M_c1(...M_c11(i)...))]. We never move
// data, so phi <- phi o M_seq with M_seq = CNOT maps applied in
// REVERSE wire order.
// ------------------------------------------------------------
static unsigned gf2_cnot_rev(unsigned v, int r) {
    for (int w = 11; w >= 0; --w) {
        int t = (w + r) % 12;
        if ((v >> (11 - w)) & 1u) v ^= 1u << (11 - t);
    }
    return v;
}

static bool ech_insert(unsigned ech[12], unsigned v) {
    for (int b = 11; b >= 0; --b) {
        if (!((v >> b) & 1u)) continue;
        if (ech[b]) { v ^= ech[b]; continue; }
        ech[b] = v; return true;
    }
    return false;
}

static void build_meta(CircMeta& meta) {
    unsigned macc[12];                       // macc[p] = phi(e_p)
    for (int p = 0; p < 12; ++p) macc[p] = 1u << p;
    for (int l = 0; l < 4; ++l) {
        // rows of phi^{-1} via Gaussian elimination over GF(2)
        unsigned row[12], aug[12];
        for (int p = 0; p < 12; ++p) {
            unsigned rr = 0;
            for (int q = 0; q < 12; ++q) rr |= ((macc[q] >> p) & 1u) << q;
            row[p] = rr; aug[p] = 1u << p;
        }
        for (int i = 0; i < 12; ++i) {
            int piv = i;
            while (!((row[piv] >> i) & 1u)) ++piv;
            unsigned t = row[i]; row[i] = row[piv]; row[piv] = t;
            t = aug[i]; aug[i] = aug[piv]; aug[piv] = t;
            for (int jj = 0; jj < 12; ++jj)
                if (jj != i && ((row[jj] >> i) & 1u)) {
                    row[jj] ^= row[i]; aug[jj] ^= aug[i];
                }
        }
        // 3 groups of 4 gates (all Rot gates in a layer commute)
        for (int grp = 0; grp < 3; ++grp) {
            GroupMeta& gm = meta.grp[l * 3 + grp];
            unsigned ech[12] = {0,0,0,0,0,0,0,0,0,0,0,0};
            for (int t = 0; t < 4; ++t) {
                int w = grp * 4 + t;
                gm.cmk[t]  = macc[11 - w];
                gm.rmk[t]  = aug[11 - w];
                gm.gidx[t] = l * 12 + w;
                ech_insert(ech, gm.cmk[t]);
            }
            // complement basis: prefer low e_j (low tid bits -> low addr bits)
            int nd = 0;
            for (int j = 0; j < 12 && nd < 8; ++j)
                if (ech_insert(ech, 1u << j)) gm.d[nd++] = 1u << j;
        }
        // phi <- phi o M_seq
        int r = l % 11 + 1;
        unsigned nmacc[12];
        for (int p = 0; p < 12; ++p) {
            unsigned u = gf2_cnot_rev(1u << p, r);
            unsigned a = 0;
            for (int q = 0; q < 12; ++q)
                if ((u >> q) & 1u) a ^= macc[q];
            nmacc[p] = a;
        }
        for (int p = 0; p < 12; ++p) macc[p] = nmacc[p];
    }
    for (int q = 0; q < 11; ++q) meta.lfmask[q] = macc[10 - q];
    meta.cz = macc[11];
}

// ------------------------------------------------------------
extern "C" void kernel_launch(void* const* d_in, const int* in_sizes, int n_in,
                              void* d_out, int out_size)
{
    const float* x   = (const float*)d_in[0];
    const float* W1  = (const float*)d_in[1];
    const float* b1  = (const float*)d_in[2];
    const float* W2  = (const float*)d_in[3];
    const float* b2  = (const float*)d_in[4];
    const float* asz = (const float*)d_in[5];
    float* out = (float*)d_out;

    CircMeta meta;
    build_meta(meta);

    dim3 g1(512 / 64, 4096 / 128);
    gemm1_kernel<<<g1, 256>>>(x, W1, b1);
    dim3 g2(128 / 64, 4096 / 128);
    gemm2_kernel<<<g2, 256>>>(W2, b2);
    circuit_kernel<<<4096, 256>>>(x, asz, out, meta);
}

// round 5
// speedup vs baseline: 1.6133x; 1.5472x over previous
#include <cuda_runtime.h>
#include <cuda_bf16.h>
#include <cstdint>
#include <math.h>

typedef unsigned long long ull;

// ============================================================
// Problem constants (fixed by the reference)
//   x:   (4096, 2048) f32      W1: (2048, 512)   b1: (512)
//   W2:  (512, 128)            b2: (128)
//   asz: (4, 12, 3)            out: (4096) f32
// ============================================================

__device__ float g_H[4096 * 512];    // relu(x@W1+b1) scratch (8 MB)
__device__ float g_com[4096 * 128];  // com_params scratch (2 MB)
__device__ __nv_bfloat16 g_xh[4096 * 2048];   // x split-hi
__device__ __nv_bfloat16 g_xl[4096 * 2048];   // x split-lo
__device__ __nv_bfloat16 g_wh[512 * 2048];    // W1^T split-hi (n-major, k contig)
__device__ __nv_bfloat16 g_wl[512 * 2048];    // W1^T split-lo

// ------------------------------------------------------------
// helpers
// ------------------------------------------------------------
__device__ __forceinline__ uint32_t smem_u32(const void* p) {
    uint32_t a;
    asm("{ .reg .u64 t; cvta.to.shared.u64 t, %1; cvt.u32.u64 %0, t; }"
        : "=r"(a) : "l"(p));
    return a;
}
__device__ __forceinline__ void cp_async16(uint32_t saddr, const void* g) {
    asm volatile("cp.async.cg.shared.global [%0], [%1], 16;"
                 :: "r"(saddr), "l"(g) : "memory");
}
#define CP_COMMIT() asm volatile("cp.async.commit_group;" ::: "memory")
#define CP_WAIT(n)  asm volatile("cp.async.wait_group %0;" :: "n"(n) : "memory")

__device__ __forceinline__ void ldm_x4(uint32_t* r, uint32_t addr) {
    asm volatile("ldmatrix.sync.aligned.m8n8.x4.shared.b16 {%0,%1,%2,%3}, [%4];"
                 : "=r"(r[0]), "=r"(r[1]), "=r"(r[2]), "=r"(r[3]) : "r"(addr));
}
__device__ __forceinline__ void ldm_x2(uint32_t* r, uint32_t addr) {
    asm volatile("ldmatrix.sync.aligned.m8n8.x2.shared.b16 {%0,%1}, [%2];"
                 : "=r"(r[0]), "=r"(r[1]) : "r"(addr));
}
__device__ __forceinline__ void mma_bf16(float* c, const uint32_t* a,
                                         const uint32_t* b) {
    asm volatile(
        "mma.sync.aligned.m16n8k16.row.col.f32.bf16.bf16.f32 "
        "{%0,%1,%2,%3}, {%4,%5,%6,%7}, {%8,%9}, {%0,%1,%2,%3};"
        : "+f"(c[0]), "+f"(c[1]), "+f"(c[2]), "+f"(c[3])
        : "r"(a[0]), "r"(a[1]), "r"(a[2]), "r"(a[3]), "r"(b[0]), "r"(b[1]));
}
__device__ __forceinline__ uint32_t swz(uint32_t byte) {   // SW128
    return byte ^ ((byte >> 3) & 0x70u);
}

// ------------------------------------------------------------
// Pre-kernels: float split into bf16 hi/lo
// ------------------------------------------------------------
__global__ void __launch_bounds__(256)
convert_x_kernel(const float* __restrict__ x)
{
    size_t i = (size_t)blockIdx.x * 256 + threadIdx.x;   // per float4
    float4 v = reinterpret_cast<const float4*>(x)[i];
    __nv_bfloat16 h0 = __float2bfloat16_rn(v.x);
    __nv_bfloat16 h1 = __float2bfloat16_rn(v.y);
    __nv_bfloat16 h2 = __float2bfloat16_rn(v.z);
    __nv_bfloat16 h3 = __float2bfloat16_rn(v.w);
    __nv_bfloat16 l0 = __float2bfloat16_rn(v.x - __bfloat162float(h0));
    __nv_bfloat16 l1 = __float2bfloat16_rn(v.y - __bfloat162float(h1));
    __nv_bfloat16 l2 = __float2bfloat16_rn(v.z - __bfloat162float(h2));
    __nv_bfloat16 l3 = __float2bfloat16_rn(v.w - __bfloat162float(h3));
    reinterpret_cast<__nv_bfloat162*>(g_xh)[i*2]   = __nv_bfloat162(h0, h1);
    reinterpret_cast<__nv_bfloat162*>(g_xh)[i*2+1] = __nv_bfloat162(h2, h3);
    reinterpret_cast<__nv_bfloat162*>(g_xl)[i*2]   = __nv_bfloat162(l0, l1);
    reinterpret_cast<__nv_bfloat162*>(g_xl)[i*2+1] = __nv_bfloat162(l2, l3);
}

__global__ void __launch_bounds__(256)
transpose_w1_kernel(const float* __restrict__ W1)
{
    __shared__ float tile[32][33];
    int n0 = blockIdx.x * 32;      // 512 / 32 = 16
    int k0 = blockIdx.y * 32;      // 2048 / 32 = 64
    int tx = threadIdx.x % 32, ty = threadIdx.x / 32;   // 32 x 8
#pragma unroll
    for (int j = 0; j < 4; ++j)
        tile[ty + 8*j][tx] = W1[(size_t)(k0 + ty + 8*j) * 512 + n0 + tx];
    __syncthreads();
#pragma unroll
    for (int j = 0; j < 4; ++j) {
        float v = tile[tx][ty + 8*j];
        __nv_bfloat16 h = __float2bfloat16_rn(v);
        __nv_bfloat16 l = __float2bfloat16_rn(v - __bfloat162float(h));
        size_t o = (size_t)(n0 + ty + 8*j) * 2048 + k0 + tx;
        g_wh[o] = h;
        g_wl[o] = l;
    }
}

// ------------------------------------------------------------
// gemm1 via mma.sync bf16 split-3: H = relu(x @ W1 + b1)
// CTA tile 128(M) x 128(N), BK=64, double-buffered cp.async, SW128.
// 8 warps: 2(M) x 4(N); warp tile 64 x 32 (4x4 m16n8k16 tiles).
// smem buffer layout: buf*65536 + {Ah:0, Al:16K, Bh:32K, Bl:48K}
// ------------------------------------------------------------
__global__ void __launch_bounds__(256)
gemm1_mma_kernel(const float* __restrict__ b1)
{
    extern __shared__ __align__(128) char smem[];
    const uint32_t sb = smem_u32(smem);
    const int tid  = threadIdx.x;
    const int wid  = tid >> 5;
    const int lane = tid & 31;
    const int wm = wid & 1, wn = wid >> 1;
    const int bm = blockIdx.y * 128, bn = blockIdx.x * 128;

    float acc[4][4][4];
#pragma unroll
    for (int mt = 0; mt < 4; ++mt)
#pragma unroll
        for (int nt = 0; nt < 4; ++nt)
#pragma unroll
            for (int j = 0; j < 4; ++j) acc[mt][nt][j] = 0.f;

    const __nv_bfloat16* srcs[4] = { g_xh, g_xl, g_wh, g_wl };

    // ---- prologue: issue chunk 0
    {
        const int kt = 0;
#pragma unroll
        for (int t = 0; t < 4; ++t) {
            int row0 = (t < 2) ? bm : bn;
            uint32_t base = sb + t * 16384u;
#pragma unroll
            for (int it = 0; it < 4; ++it) {
                int id = tid + it * 256;
                int r = id >> 3, blk = id & 7;
                cp_async16(base + swz((uint32_t)(r * 128 + blk * 16)),
                           srcs[t] + (size_t)(row0 + r) * 2048 + kt + blk * 8);
            }
        }
        CP_COMMIT();
    }

#pragma unroll 1
    for (int c = 0; c < 32; ++c) {
        if (c + 1 < 32) {
            const int kt = (c + 1) * 64;
            const uint32_t bufo = (uint32_t)((c + 1) & 1) * 65536u;
#pragma unroll
            for (int t = 0; t < 4; ++t) {
                int row0 = (t < 2) ? bm : bn;
                uint32_t base = sb + bufo + t * 16384u;
#pragma unroll
                for (int it = 0; it < 4; ++it) {
                    int id = tid + it * 256;
                    int r = id >> 3, blk = id & 7;
                    cp_async16(base + swz((uint32_t)(r * 128 + blk * 16)),
                               srcs[t] + (size_t)(row0 + r) * 2048 + kt + blk * 8);
                }
            }
            CP_COMMIT();
            CP_WAIT(1);
        } else {
            CP_WAIT(0);
        }
        __syncthreads();

        const uint32_t base = sb + (uint32_t)(c & 1) * 65536u;
#pragma unroll
        for (int kk = 0; kk < 4; ++kk) {
            uint32_t ah[4][4], al[4][4], bh[4][2], bl[4][2];
#pragma unroll
            for (int mt = 0; mt < 4; ++mt) {
                uint32_t byte = (uint32_t)((wm * 64 + mt * 16 + (lane & 15)) * 128
                                           + (kk * 2 + (lane >> 4)) * 16);
                uint32_t ad = base + swz(byte);
                ldm_x4(ah[mt], ad);
                ldm_x4(al[mt], ad + 16384u);
            }
#pragma unroll
            for (int nt = 0; nt < 4; ++nt) {
                uint32_t byte = (uint32_t)((wn * 32 + nt * 8 + (lane & 7)) * 128
                                           + (kk * 2 + ((lane >> 3) & 1)) * 16);
                uint32_t bd = base + 32768u + swz(byte);
                ldm_x2(bh[nt], bd);
                ldm_x2(bl[nt], bd + 16384u);
            }
#pragma unroll
            for (int mt = 0; mt < 4; ++mt)
#pragma unroll
                for (int nt = 0; nt < 4; ++nt) {
                    mma_bf16(acc[mt][nt], ah[mt], bh[nt]);
                    mma_bf16(acc[mt][nt], ah[mt], bl[nt]);
                    mma_bf16(acc[mt][nt], al[mt], bh[nt]);
                }
        }
        __syncthreads();
    }

    // ---- epilogue: bias + relu
#pragma unroll
    for (int mt = 0; mt < 4; ++mt) {
        int row = bm + wm * 64 + mt * 16 + (lane >> 2);
#pragma unroll
        for (int nt = 0; nt < 4; ++nt) {
            int col = bn + wn * 32 + nt * 8 + (lane & 3) * 2;
            float b0 = b1[col], bq = b1[col + 1];
            float2 v0 = make_float2(fmaxf(acc[mt][nt][0] + b0, 0.f),
                                    fmaxf(acc[mt][nt][1] + bq, 0.f));
            float2 v1 = make_float2(fmaxf(acc[mt][nt][2] + b0, 0.f),
                                    fmaxf(acc[mt][nt][3] + bq, 0.f));
            *reinterpret_cast<float2*>(&g_H[(size_t)row * 512 + col])       = v0;
            *reinterpret_cast<float2*>(&g_H[(size_t)(row + 8) * 512 + col]) = v1;
        }
    }
}

// ------------------------------------------------------------
// f32x2 helpers + fp32 SGEMM (gemm2)
// ------------------------------------------------------------
__device__ __forceinline__ ull f2mul(ull a, ull b) {
    ull d; asm("mul.rn.f32x2 %0, %1, %2;" : "=l"(d) : "l"(a), "l"(b)); return d;
}
__device__ __forceinline__ ull f2fma(ull a, ull b, ull c) {
    ull d; asm("fma.rn.f32x2 %0, %1, %2, %3;" : "=l"(d) : "l"(a), "l"(b), "l"(c)); return d;
}
__device__ __forceinline__ ull pack2(float lo, float hi) {
    ull r; asm("mov.b64 %0, {%1, %2};" : "=l"(r) : "f"(lo), "f"(hi)); return r;
}
__device__ __forceinline__ float2 unpack2(ull v) {
    float2 r; asm("mov.b64 {%0, %1}, %2;" : "=f"(r.x), "=f"(r.y) : "l"(v)); return r;
}
__device__ __forceinline__ ull uswap(ull v) {
    float2 r = unpack2(v);
    return pack2(r.y, r.x);
}

template<int BM, int BN, int BK, int TM, int TN, bool RELU>
__device__ __forceinline__ void sgemm_body(
    const float* __restrict__ A, const float* __restrict__ Bm,
    const float* __restrict__ bias, float* __restrict__ C,
    int M, int N, int K)
{
    __shared__ float As[BK][BM];
    __shared__ float Bs[BK][BN];
    const int tid = threadIdx.x;
    const int NX = BN / TN;
    const int tx = tid % NX;
    const int ty = tid / NX;
    const int bm = blockIdx.y * BM;
    const int bn = blockIdx.x * BN;

    ull acc[TM / 2][TN];
#pragma unroll
    for (int i = 0; i < TM / 2; ++i)
#pragma unroll
        for (int j = 0; j < TN; ++j) acc[i][j] = 0ull;

    for (int kt = 0; kt < K; kt += BK) {
#pragma unroll
        for (int l = 0; l < (BM * BK) / (256 * 4); ++l) {
            int id  = tid + l * 256;
            int row = id / (BK / 4);
            int c   = id % (BK / 4);
            float4 v = *reinterpret_cast<const float4*>(
                A + (size_t)(bm + row) * K + kt + c * 4);
            As[c*4+0][row] = v.x; As[c*4+1][row] = v.y;
            As[c*4+2][row] = v.z; As[c*4+3][row] = v.w;
        }
#pragma unroll
        for (int l = 0; l < (BK * BN) / (256 * 4); ++l) {
            int id = tid + l * 256;
            int kr = id / (BN / 4);
            int c  = id % (BN / 4);
            *reinterpret_cast<float4*>(&Bs[kr][c*4]) =
                *reinterpret_cast<const float4*>(
                    Bm + (size_t)(kt + kr) * N + bn + c * 4);
        }
        __syncthreads();
#pragma unroll
        for (int k = 0; k < BK; ++k) {
            ull ra[TM / 2];
            float rb[TN];
#pragma unroll
            for (int i = 0; i < TM / 2; ++i)
                ra[i] = *reinterpret_cast<const ull*>(&As[k][ty*TM + 2*i]);
#pragma unroll
            for (int j = 0; j < TN; j += 4)
                *reinterpret_cast<float4*>(&rb[j]) =
                    *reinterpret_cast<const float4*>(&Bs[k][tx*TN + j]);
#pragma unroll
            for (int j = 0; j < TN; ++j) {
                ull rbb = pack2(rb[j], rb[j]);
#pragma unroll
                for (int i = 0; i < TM / 2; ++i)
                    acc[i][j] = f2fma(ra[i], rbb, acc[i][j]);
            }
        }
        __syncthreads();
    }
#pragma unroll
    for (int i = 0; i < TM / 2; ++i) {
        int row = bm + ty * TM + 2 * i;
#pragma unroll
        for (int j = 0; j < TN; ++j) {
            int col = bn + tx * TN + j;
            float2 u = unpack2(acc[i][j]);
            float vlo = u.x + bias[col];
            float vhi = u.y + bias[col];
            if (RELU) { vlo = fmaxf(vlo, 0.f); vhi = fmaxf(vhi, 0.f); }
            C[(size_t)row * N + col]       = vlo;
            C[(size_t)(row + 1) * N + col] = vhi;
        }
    }
}

__global__ void __launch_bounds__(256)
gemm2_kernel(const float* __restrict__ W2, const float* __restrict__ b2)
{
    sgemm_body<128, 64, 16, 8, 4, false>(g_H, W2, b2, g_com, 4096, 128, 512);
}

// ------------------------------------------------------------
// Quantum circuit kernel (same as R3 kernel; host d-basis improved)
// ------------------------------------------------------------
struct GroupMeta {
    unsigned cmk[4];
    unsigned rmk[4];
    unsigned d[8];
    int      gidx[4];
};
struct CircMeta {
    GroupMeta grp[12];
    unsigned lfmask[11];
    unsigned cz;
};

__global__ void __launch_bounds__(256)
circuit_kernel(const float* __restrict__ x, const float* __restrict__ asz,
               float* __restrict__ out, CircMeta meta)
{
    __shared__ float2 st[4096];
    __shared__ ull    mats[48][8];
    __shared__ float  wsum[8];
    const int b   = blockIdx.x;
    const int tid = threadIdx.x;
    ull* stq = reinterpret_cast<ull*>(st);

    if (tid < 48) {
        float phi = asz[tid*3+0], th = asz[tid*3+1], om = asz[tid*3+2];
        float c, s, cp, sp, cm, sm;
        sincosf(0.5f * th, &s, &c);
        sincosf(0.5f * (phi + om), &sp, &cp);
        sincosf(0.5f * (phi - om), &sm, &cm);
        float2 m00 = make_float2( cp * c, -sp * c);
        float2 m01 = make_float2(-cm * s, -sm * s);
        float2 m10 = make_float2( cm * s, -sm * s);
        float2 m11 = make_float2( cp * c,  sp * c);
        mats[tid][0] = pack2(m00.x, m00.x); mats[tid][1] = pack2(-m00.y, m00.y);
        mats[tid][2] = pack2(m01.x, m01.x); mats[tid][3] = pack2(-m01.y, m01.y);
        mats[tid][4] = pack2(m10.x, m10.x); mats[tid][5] = pack2(-m10.y, m10.y);
        mats[tid][6] = pack2(m11.x, m11.x); mats[tid][7] = pack2(-m11.y, m11.y);
    }
#pragma unroll
    for (int i = 0; i < 16; ++i) st[tid + i * 256] = make_float2(0.f, 0.f);
    __syncthreads();

    if (tid < 128) {
        const float inv = 0.08838834764831844f;  // 2^-3.5
        float a = 0.5f * g_com[b * 128 + tid];
        float sa, ca; sincosf(a, &sa, &ca);
        int j = (int)(__brev((unsigned)tid) >> 25);  // rev7
        st[j * 16]        = make_float2(ca * inv, 0.f);
        st[2048 + j * 16] = make_float2(sa * inv, 0.f);
    }
    __syncthreads();

#pragma unroll 1
    for (int G = 0; G < 12; ++G) {
        const GroupMeta& gm = meta.grp[G];
        unsigned rep = 0;
#pragma unroll
        for (int j = 0; j < 8; ++j)
            rep ^= ((tid >> j) & 1u) ? gm.d[j] : 0u;

        unsigned idx[16];
#pragma unroll
        for (int bb = 0; bb < 16; ++bb) {
            unsigned o = rep;
            if (bb & 1) o ^= gm.cmk[0];
            if (bb & 2) o ^= gm.cmk[1];
            if (bb & 4) o ^= gm.cmk[2];
            if (bb & 8) o ^= gm.cmk[3];
            idx[bb] = o;
        }
        ull v[16];
#pragma unroll
        for (int bb = 0; bb < 16; ++bb) v[bb] = stq[idx[bb]];

#pragma unroll
        for (int gg = 0; gg < 4; ++gg) {
            const ull* mp = mats[gm.gidx[gg]];
            bool lb = (__popc(gm.rmk[gg] & rep) & 1) != 0;
            ull a0r = lb ? mp[6] : mp[0], a0i = lb ? mp[7] : mp[1];
            ull a1r = lb ? mp[4] : mp[2], a1i = lb ? mp[5] : mp[3];
            ull b0r = lb ? mp[2] : mp[4], b0i = lb ? mp[3] : mp[5];
            ull b1r = lb ? mp[0] : mp[6], b1i = lb ? mp[1] : mp[7];
            const unsigned bit = 1u << gg;
#pragma unroll
            for (int bb = 0; bb < 16; ++bb) {
                if (bb & bit) continue;
                ull s0 = v[bb], s1 = v[bb ^ bit];
                ull s0s = uswap(s0), s1s = uswap(s1);
                ull n0 = f2mul(a0r, s0);
                n0 = f2fma(a0i, s0s, n0);
                n0 = f2fma(a1r, s1, n0);
                n0 = f2fma(a1i, s1s, n0);
                ull n1 = f2mul(b0r, s0);
                n1 = f2fma(b0i, s0s, n1);
                n1 = f2fma(b1r, s1, n1);
                n1 = f2fma(b1i, s1s, n1);
                v[bb] = n0; v[bb ^ bit] = n1;
            }
        }
#pragma unroll
        for (int bb = 0; bb < 16; ++bb) stq[idx[bb]] = v[bb];
        __syncthreads();
    }

    float acc = 0.f;
#pragma unroll
    for (int i = 0; i < 8; ++i) {
        unsigned idx = tid + i * 256;
        unsigned m0 = 0;
#pragma unroll
        for (int q = 0; q < 11; ++q)
            m0 ^= (0u - ((idx >> q) & 1u)) & meta.lfmask[q];
        unsigned m1 = m0 ^ meta.cz;
        float2 s0 = st[m0];
        float2 s1 = st[m1];
        float xv = x[(size_t)b * 2048 + idx];
        float sv, cv;
        sincosf(xv, &sv, &cv);
        acc += cv * ((s1.x*s1.x + s1.y*s1.y) - (s0.x*s0.x + s0.y*s0.y))
             - 2.f * sv * (s0.x*s1.x + s0.y*s1.y);
    }
#pragma unroll
    for (int o = 16; o > 0; o >>= 1)
        acc += __shfl_down_sync(0xffffffffu, acc, o);
    if ((tid & 31) == 0) wsum[tid >> 5] = acc;
    __syncthreads();
    if (tid == 0) {
        float v = 0.f;
#pragma unroll
        for (int w = 0; w < 8; ++w) v += wsum[w];
        out[b] = v;
    }
}

// ------------------------------------------------------------
// Host: GF(2) bookkeeping
// ------------------------------------------------------------
struct Ech {
    unsigned e[12];
    Ech() { for (int i = 0; i < 12; ++i) e[i] = 0; }
    unsigned reduce(unsigned v) const {
        for (int b = 11; b >= 0; --b)
            if (((v >> b) & 1u) && e[b]) v ^= e[b];
        return v;
    }
    bool insert(unsigned v) {
        v = reduce(v);
        if (!v) return false;
        int b = 11;
        while (!((v >> b) & 1u)) --b;
        e[b] = v;
        return true;
    }
};

static unsigned gf2_cnot_rev(unsigned v, int r) {
    for (int w = 11; w >= 0; --w) {
        int t = (w + r) % 12;
        if ((v >> (11 - w)) & 1u) v ^= 1u << (11 - t);
    }
    return v;
}

static void build_meta(CircMeta& meta) {
    unsigned macc[12];
    for (int p = 0; p < 12; ++p) macc[p] = 1u << p;
    for (int l = 0; l < 4; ++l) {
        unsigned row[12], aug[12];
        for (int p = 0; p < 12; ++p) {
            unsigned rr = 0;
            for (int q = 0; q < 12; ++q) rr |= ((macc[q] >> p) & 1u) << q;
            row[p] = rr; aug[p] = 1u << p;
        }
        for (int i = 0; i < 12; ++i) {
            int piv = i;
            while (!((row[piv] >> i) & 1u)) ++piv;
            unsigned t = row[i]; row[i] = row[piv]; row[piv] = t;
            t = aug[i]; aug[i] = aug[piv]; aug[piv] = t;
            for (int jj = 0; jj < 12; ++jj)
                if (jj != i && ((row[jj] >> i) & 1u)) {
                    row[jj] ^= row[i]; aug[jj] ^= aug[i];
                }
        }
        for (int grp = 0; grp < 3; ++grp) {
            GroupMeta& gm = meta.grp[l * 3 + grp];
            Ech ech;
            for (int t = 0; t < 4; ++t) {
                int w = grp * 4 + t;
                gm.cmk[t]  = macc[11 - w];
                gm.rmk[t]  = aug[11 - w];
                gm.gidx[t] = l * 12 + w;
                ech.insert(gm.cmk[t]);
            }
            // d[0..4] = lane vectors: independent in full space AND with
            // linearly independent projections onto address bits 0..4
            // -> all 32 lanes hit distinct ull-index mod 32 (conflict-free
            //    LDS.64 / STS.64 for every orbit offset).
            int nd = 0;
            unsigned proje[5] = {0, 0, 0, 0, 0};
            for (unsigned v = 1; v < 4096 && nd < 5; ++v) {
                if (ech.reduce(v) == 0) continue;        // in span
                unsigned p = v & 31u;
                for (int b = 4; b >= 0; --b)
                    if (((p >> b) & 1u) && proje[b]) p ^= proje[b];
                if (p == 0) continue;                    // dependent proj
                ech.insert(v);
                int pb = 4;
                while (!((p >> pb) & 1u)) --pb;
                proje[pb] = p;
                gm.d[nd++] = v;
            }
            // fill remaining (warp bits, no conflict constraint)
            for (unsigned v = 1; v < 4096 && nd < 8; ++v)
                if (ech.insert(v)) gm.d[nd++] = v;
        }
        int r = l % 11 + 1;
        unsigned nmacc[12];
        for (int p = 0; p < 12; ++p) {
            unsigned u = gf2_cnot_rev(1u << p, r);
            unsigned a = 0;
            for (int q = 0; q < 12; ++q)
                if ((u >> q) & 1u) a ^= macc[q];
            nmacc[p] = a;
        }
        for (int p = 0; p < 12; ++p) macc[p] = nmacc[p];
    }
    for (int q = 0; q < 11; ++q) meta.lfmask[q] = macc[10 - q];
    meta.cz = macc[11];
}

// ------------------------------------------------------------
extern "C" void kernel_launch(void* const* d_in, const int* in_sizes, int n_in,
                              void* d_out, int out_size)
{
    const float* x   = (const float*)d_in[0];
    const float* W1  = (const float*)d_in[1];
    const float* b1  = (const float*)d_in[2];
    const float* W2  = (const float*)d_in[3];
    const float* b2  = (const float*)d_in[4];
    const float* asz = (const float*)d_in[5];
    float* out = (float*)d_out;

    CircMeta meta;
    build_meta(meta);

    cudaFuncSetAttribute(gemm1_mma_kernel,
                         cudaFuncAttributeMaxDynamicSharedMemorySize, 131072);

    convert_x_kernel<<<4096 * 2048 / 4 / 256, 256>>>(x);
    transpose_w1_kernel<<<dim3(16, 64), 256>>>(W1);
    gemm1_mma_kernel<<<dim3(4, 32), 256, 131072>>>(b1);
    dim3 g2(128 / 64, 4096 / 128);
    gemm2_kernel<<<g2, 256>>>(W2, b2);
    circuit_kernel<<<4096, 256>>>(x, asz, out, meta);
}